// round 5
// baseline (speedup 1.0000x reference)
#include <cuda_runtime.h>
#include <math.h>

// Problem constants
#define BATCH 8
#define HH 256
#define WW 256
#define GY 512
#define GX 512
#define JJ 7
#define NS 100000
#define NBINS 512            // 16 y-tiles (32 rows) x 32 x-tiles (16 cols)

// Scratch (allocation forbidden -> device globals)
__device__ float2 g_tmp[HH * GX * BATCH];    // [y][kx][b]   8 MB
__device__ float2 g_ghat[GY * GX * BATCH];   // [ky][x][b]  16 MB
__device__ float2 g_tw[512];                 // W_512^j twiddle table
__device__ int g_binCount[NBINS];
__device__ int g_binStart[NBINS];
__device__ int g_binCursor[NBINS];
__device__ int g_order[NS];

// ---------------- complex helpers ----------------
__device__ __forceinline__ float2 cadd(float2 a, float2 b){ return make_float2(a.x+b.x, a.y+b.y); }
__device__ __forceinline__ float2 csub(float2 a, float2 b){ return make_float2(a.x-b.x, a.y-b.y); }
__device__ __forceinline__ float2 cmul(float2 a, float2 w){ return make_float2(a.x*w.x - a.y*w.y, a.x*w.y + a.y*w.x); }
__device__ __forceinline__ float2 mulnegi(float2 a){ return make_float2(a.y, -a.x); }

#define KC 0.70710678118654752440f

// radix-8 DIF butterfly: y[r] = sum_s v[s] * w8^(r*s)
__device__ __forceinline__ void radix8_dif(const float2 v[8], float2 y[8]) {
    float2 a0=cadd(v[0],v[4]), a1=cadd(v[1],v[5]), a2=cadd(v[2],v[6]), a3=cadd(v[3],v[7]);
    float2 t1=csub(v[1],v[5]), t2=csub(v[2],v[6]), t3=csub(v[3],v[7]);
    float2 b0=csub(v[0],v[4]);
    float2 b1=make_float2(KC*(t1.x+t1.y), KC*(t1.y-t1.x));
    float2 b2=mulnegi(t2);
    float2 b3=make_float2(KC*(t3.y-t3.x), -KC*(t3.x+t3.y));
    float2 c0=cadd(a0,a2), c1=cadd(a1,a3), c2=csub(a0,a2), c3=mulnegi(csub(a1,a3));
    float2 d0=cadd(b0,b2), d1=cadd(b1,b3), d2=csub(b0,b2), d3=mulnegi(csub(b1,b3));
    y[0]=cadd(c0,c1); y[4]=csub(c0,c1);
    y[2]=cadd(c2,c3); y[6]=csub(c2,c3);
    y[1]=cadd(d0,d1); y[5]=csub(d0,d1);
    y[3]=cadd(d2,d3); y[7]=csub(d2,d3);
}

// radix-8 DIF with v[4..7] == 0 (zero-padded input)
__device__ __forceinline__ void radix8_dif_half(const float2 v[4], float2 y[8]) {
    float2 a0=v[0], a1=v[1], a2=v[2], a3=v[3];
    float2 b0=v[0];
    float2 b1=make_float2(KC*(v[1].x+v[1].y), KC*(v[1].y-v[1].x));
    float2 b2=mulnegi(v[2]);
    float2 b3=make_float2(KC*(v[3].y-v[3].x), -KC*(v[3].x+v[3].y));
    float2 c0=cadd(a0,a2), c1=cadd(a1,a3), c2=csub(a0,a2), c3=mulnegi(csub(a1,a3));
    float2 d0=cadd(b0,b2), d1=cadd(b1,b3), d2=csub(b0,b2), d3=mulnegi(csub(b1,b3));
    y[0]=cadd(c0,c1); y[4]=csub(c0,c1);
    y[2]=cadd(c2,c3); y[6]=csub(c2,c3);
    y[1]=cadd(d0,d1); y[5]=csub(d0,d1);
    y[3]=cadd(d2,d3); y[7]=csub(d2,d3);
}

// padded physical smem index (breaks stride-8/64 bank conflicts)
__device__ __forceinline__ int phys(int i)   { return i + (i>>3) + (i>>6); }  // max 581
__device__ __forceinline__ int physIn(int i) { return i + (i>>3); }           // max 286

#define COLSZ  585
#define COLSZI 289

// ---------------------------------------------------------------------------
// init: twiddle table + zero bin counters. 1 block x 512 threads.
// ---------------------------------------------------------------------------
__global__ void init_kernel() {
    int t = threadIdx.x;
    float ang = (-2.0f * (float)M_PI / 512.0f) * (float)t;
    float s, c;
    sincosf(ang, &s, &c);
    g_tw[t] = make_float2(c, s);
    g_binCount[t] = 0;
    g_binCursor[t] = 0;
}

// ---------------------------------------------------------------------------
// binning passes
// ---------------------------------------------------------------------------
__global__ void count_kernel(const int* __restrict__ iy, const int* __restrict__ ix) {
    int n = blockIdx.x * blockDim.x + threadIdx.x;
    if (n >= NS) return;
    int by = iy[n * JJ + 3] >> 5;      // 0..15
    int bx = ix[n * JJ + 3] >> 4;      // 0..31
    atomicAdd(&g_binCount[(by << 5) | bx], 1);
}

__global__ void scan_kernel() {       // 1 block x 512
    __shared__ int s[NBINS];
    int t = threadIdx.x;
    int my = g_binCount[t];
    s[t] = my;
    __syncthreads();
    #pragma unroll
    for (int off = 1; off < NBINS; off <<= 1) {
        int v = (t >= off) ? s[t - off] : 0;
        __syncthreads();
        s[t] += v;
        __syncthreads();
    }
    g_binStart[t] = s[t] - my;        // exclusive prefix
}

__global__ void place_kernel(const int* __restrict__ iy, const int* __restrict__ ix) {
    int n = blockIdx.x * blockDim.x + threadIdx.x;
    if (n >= NS) return;
    int by = iy[n * JJ + 3] >> 5;
    int bx = ix[n * JJ + 3] >> 4;
    int bin = (by << 5) | bx;
    int pos = atomicAdd(&g_binCursor[bin], 1);
    g_order[g_binStart[bin] + pos] = n;
}

// ---------------------------------------------------------------------------
// Stage A: apodize + row FFT (512-pt, radix-8 x3, table twiddles).
// Block = (y, batch-group of 4); 256 threads = 4 columns x 64.
// ---------------------------------------------------------------------------
__global__ void __launch_bounds__(256) row_fft_kernel(
    const float* __restrict__ xr, const float* __restrict__ xi,
    const float* __restrict__ scy, const float* __restrict__ scx)
{
    __shared__ float2 sh[4][COLSZ];
    int y  = blockIdx.x;
    int bg = blockIdx.y;
    int t  = threadIdx.x;
    int c  = t >> 6;
    int u  = t & 63;
    int b  = bg * 4 + c;

    const float* rr = xr + ((size_t)b * HH + y) * WW;
    const float* ii = xi + ((size_t)b * HH + y) * WW;
    float syv = scy[y] * (1.0f / 512.0f);

    float2 v[8], yo[8];
    float2 vh[4];
    #pragma unroll
    for (int s = 0; s < 4; s++) {
        int n = u + 64 * s;
        float sc = syv * scx[n];
        vh[s] = make_float2(rr[n] * sc, ii[n] * sc);
    }
    // pass 1 (span 64, upper half zero)
    radix8_dif_half(vh, yo);
    sh[c][phys(u)] = yo[0];
    #pragma unroll
    for (int r = 1; r < 8; r++)
        sh[c][phys(64 * r + u)] = cmul(yo[r], g_tw[(u * r) & 511]);
    __syncthreads();

    // pass 2 (span 8)
    int g = u >> 3, q = u & 7;
    #pragma unroll
    for (int s = 0; s < 8; s++) v[s] = sh[c][phys(64 * g + q + 8 * s)];
    __syncthreads();
    radix8_dif(v, yo);
    sh[c][phys(64 * g + q)] = yo[0];
    #pragma unroll
    for (int r = 1; r < 8; r++)
        sh[c][phys(64 * g + 8 * r + q)] = cmul(yo[r], g_tw[(8 * q * r) & 511]);
    __syncthreads();

    // pass 3 (span 1), store at natural frequency index
    #pragma unroll
    for (int s = 0; s < 8; s++) v[s] = sh[c][phys(8 * u + s)];
    __syncthreads();
    radix8_dif(v, yo);
    int r1 = u >> 3, r2 = u & 7;
    #pragma unroll
    for (int r = 0; r < 8; r++)
        sh[c][phys(64 * r + 8 * r2 + r1)] = yo[r];
    __syncthreads();

    // coalesced writeout: tmp[y][kx][b]
    float2* outp = g_tmp + (size_t)y * GX * BATCH + bg * 4;
    #pragma unroll
    for (int it = 0; it < 8; it++) {
        int i  = it * 256 + t;
        int kx = i >> 2;
        int cc = i & 3;
        outp[(size_t)kx * BATCH + cc] = sh[cc][phys(kx)];
    }
}

// ---------------------------------------------------------------------------
// Stage B: column FFT. Block = (x, batch-group of 4).
// ---------------------------------------------------------------------------
__global__ void __launch_bounds__(256) col_fft_kernel()
{
    __shared__ float2 sh[4][COLSZ];
    __shared__ float2 shin[4][COLSZI];
    int x  = blockIdx.x;
    int bg = blockIdx.y;
    int t  = threadIdx.x;
    int c  = t >> 6;
    int u  = t & 63;

    // coalesced staging of the 256 nonzero column entries
    const float2* inp = g_tmp + (size_t)x * BATCH + bg * 4;
    #pragma unroll
    for (int it = 0; it < 4; it++) {
        int i  = it * 256 + t;
        int yy = i >> 2;
        int cc = i & 3;
        shin[cc][physIn(yy)] = inp[(size_t)yy * GX * BATCH + cc];
    }
    __syncthreads();

    float2 v[8], yo[8];
    float2 vh[4];
    #pragma unroll
    for (int s = 0; s < 4; s++) vh[s] = shin[c][physIn(u + 64 * s)];

    radix8_dif_half(vh, yo);
    sh[c][phys(u)] = yo[0];
    #pragma unroll
    for (int r = 1; r < 8; r++)
        sh[c][phys(64 * r + u)] = cmul(yo[r], g_tw[(u * r) & 511]);
    __syncthreads();

    int g = u >> 3, q = u & 7;
    #pragma unroll
    for (int s = 0; s < 8; s++) v[s] = sh[c][phys(64 * g + q + 8 * s)];
    __syncthreads();
    radix8_dif(v, yo);
    sh[c][phys(64 * g + q)] = yo[0];
    #pragma unroll
    for (int r = 1; r < 8; r++)
        sh[c][phys(64 * g + 8 * r + q)] = cmul(yo[r], g_tw[(8 * q * r) & 511]);
    __syncthreads();

    #pragma unroll
    for (int s = 0; s < 8; s++) v[s] = sh[c][phys(8 * u + s)];
    __syncthreads();
    radix8_dif(v, yo);
    int r1 = u >> 3, r2 = u & 7;
    #pragma unroll
    for (int r = 0; r < 8; r++)
        sh[c][phys(64 * r + 8 * r2 + r1)] = yo[r];
    __syncthreads();

    // writeout: ghat[ky][x][b]
    float2* outp = g_ghat + (size_t)x * BATCH + bg * 4;
    #pragma unroll
    for (int it = 0; it < 8; it++) {
        int i  = it * 256 + t;
        int ky = i >> 2;
        int cc = i & 3;
        outp[((size_t)ky * GX) * BATCH + cc] = sh[cc][phys(ky)];
    }
}

// ---------------------------------------------------------------------------
// Stage C: binned gather. One 1024-thread block per bin; the bin's 7x7
// support region (~53 KB) stays L1-resident (<=2 blocks/SM).
// Lane = (sample, batch).
// ---------------------------------------------------------------------------
__global__ void __launch_bounds__(1024) gather_kernel(
    const float* __restrict__ wy, const float* __restrict__ wx,
    const float* __restrict__ phr, const float* __restrict__ phi,
    const int* __restrict__ iy, const int* __restrict__ ix,
    float* __restrict__ out)
{
    int bin   = blockIdx.x;
    int start = g_binStart[bin];
    int cnt   = g_binCount[bin];
    int t  = threadIdx.x;
    int b  = t & 7;
    int sl = t >> 3;                 // 0..127

    for (int s0 = sl; s0 < cnt; s0 += 128) {
        int n = g_order[start + s0];

        int   ixv[JJ];
        float wxv[JJ];
        #pragma unroll
        for (int k = 0; k < JJ; k++) {
            ixv[k] = ix[(size_t)n * JJ + k];
            wxv[k] = wx[(size_t)n * JJ + k];
        }

        float ax = 0.f, ay = 0.f;
        #pragma unroll
        for (int j = 0; j < JJ; j++) {
            int   iyj = iy[(size_t)n * JJ + j];
            float wj  = wy[(size_t)n * JJ + j];
            const float2* rowp = g_ghat + (size_t)iyj * GX * BATCH + b;
            #pragma unroll
            for (int k = 0; k < JJ; k++) {
                float2 vv = rowp[(size_t)ixv[k] * BATCH];
                float  w  = wj * wxv[k];
                ax += w * vv.x;
                ay += w * vv.y;
            }
        }

        float pr = phr[n], pi = phi[n];
        float re = ax * pr - ay * pi;
        float im = ax * pi + ay * pr;
        float2* o = (float2*)(out + ((size_t)b * NS + n) * 2);
        *o = make_float2(re, im);
    }
}

// ---------------------------------------------------------------------------
// inputs: 0:xr 1:xi 2:sc_y 3:sc_x 4:wy 5:wx 6:phr 7:phi 8:iy 9:ix
// ---------------------------------------------------------------------------
extern "C" void kernel_launch(void* const* d_in, const int* in_sizes, int n_in,
                              void* d_out, int out_size)
{
    const float* xr  = (const float*)d_in[0];
    const float* xi  = (const float*)d_in[1];
    const float* scy = (const float*)d_in[2];
    const float* scx = (const float*)d_in[3];
    const float* wy  = (const float*)d_in[4];
    const float* wx  = (const float*)d_in[5];
    const float* phr = (const float*)d_in[6];
    const float* phi = (const float*)d_in[7];
    const int*   iy  = (const int*)d_in[8];
    const int*   ix  = (const int*)d_in[9];
    float* out = (float*)d_out;

    init_kernel<<<1, 512>>>();

    int nb = (NS + 255) / 256;
    count_kernel<<<nb, 256>>>(iy, ix);
    scan_kernel<<<1, NBINS>>>();
    place_kernel<<<nb, 256>>>(iy, ix);

    dim3 rowGrid(HH, 2);
    row_fft_kernel<<<rowGrid, 256>>>(xr, xi, scy, scx);

    dim3 colGrid(GX, 2);
    col_fft_kernel<<<colGrid, 256>>>();

    gather_kernel<<<NBINS, 1024>>>(wy, wx, phr, phi, iy, ix, out);
}

// round 6
// speedup vs baseline: 1.3406x; 1.3406x over previous
#include <cuda_runtime.h>
#include <cuda_fp16.h>
#include <math.h>

// Problem constants
#define BATCH 8
#define HH 256
#define WW 256
#define GY 512
#define GX 512
#define JJ 7
#define NS 100000

// Scratch (allocation forbidden -> device globals)
__device__ float2  g_tmp[HH * GX * BATCH];    // [y][kx][b]  fp32, 8 MB
__device__ __half2 g_ghat[GY * GX * BATCH];   // [ky][x][b]  fp16, 8 MB
__device__ float2  g_tw[512];                 // W_512^j twiddle table

// ---------------- complex helpers ----------------
__device__ __forceinline__ float2 cadd(float2 a, float2 b){ return make_float2(a.x+b.x, a.y+b.y); }
__device__ __forceinline__ float2 csub(float2 a, float2 b){ return make_float2(a.x-b.x, a.y-b.y); }
__device__ __forceinline__ float2 cmul(float2 a, float2 w){ return make_float2(a.x*w.x - a.y*w.y, a.x*w.y + a.y*w.x); }
__device__ __forceinline__ float2 mulnegi(float2 a){ return make_float2(a.y, -a.x); }

#define KC 0.70710678118654752440f

// radix-8 DIF butterfly: y[r] = sum_s v[s] * w8^(r*s)
__device__ __forceinline__ void radix8_dif(const float2 v[8], float2 y[8]) {
    float2 a0=cadd(v[0],v[4]), a1=cadd(v[1],v[5]), a2=cadd(v[2],v[6]), a3=cadd(v[3],v[7]);
    float2 t1=csub(v[1],v[5]), t2=csub(v[2],v[6]), t3=csub(v[3],v[7]);
    float2 b0=csub(v[0],v[4]);
    float2 b1=make_float2(KC*(t1.x+t1.y), KC*(t1.y-t1.x));
    float2 b2=mulnegi(t2);
    float2 b3=make_float2(KC*(t3.y-t3.x), -KC*(t3.x+t3.y));
    float2 c0=cadd(a0,a2), c1=cadd(a1,a3), c2=csub(a0,a2), c3=mulnegi(csub(a1,a3));
    float2 d0=cadd(b0,b2), d1=cadd(b1,b3), d2=csub(b0,b2), d3=mulnegi(csub(b1,b3));
    y[0]=cadd(c0,c1); y[4]=csub(c0,c1);
    y[2]=cadd(c2,c3); y[6]=csub(c2,c3);
    y[1]=cadd(d0,d1); y[5]=csub(d0,d1);
    y[3]=cadd(d2,d3); y[7]=csub(d2,d3);
}

// radix-8 DIF with v[4..7] == 0 (zero-padded input)
__device__ __forceinline__ void radix8_dif_half(const float2 v[4], float2 y[8]) {
    float2 a0=v[0], a1=v[1], a2=v[2], a3=v[3];
    float2 b0=v[0];
    float2 b1=make_float2(KC*(v[1].x+v[1].y), KC*(v[1].y-v[1].x));
    float2 b2=mulnegi(v[2]);
    float2 b3=make_float2(KC*(v[3].y-v[3].x), -KC*(v[3].x+v[3].y));
    float2 c0=cadd(a0,a2), c1=cadd(a1,a3), c2=csub(a0,a2), c3=mulnegi(csub(a1,a3));
    float2 d0=cadd(b0,b2), d1=cadd(b1,b3), d2=csub(b0,b2), d3=mulnegi(csub(b1,b3));
    y[0]=cadd(c0,c1); y[4]=csub(c0,c1);
    y[2]=cadd(c2,c3); y[6]=csub(c2,c3);
    y[1]=cadd(d0,d1); y[5]=csub(d0,d1);
    y[3]=cadd(d2,d3); y[7]=csub(d2,d3);
}

// padded physical smem index (breaks stride-8/64 bank conflicts)
__device__ __forceinline__ int phys(int i)   { return i + (i>>3) + (i>>6); }  // max 581
__device__ __forceinline__ int physIn(int i) { return i + (i>>3); }           // max 286

#define COLSZ  585
#define COLSZI 289

// ---------------------------------------------------------------------------
// init: twiddle table. 1 block x 512 threads.
// ---------------------------------------------------------------------------
__global__ void init_kernel() {
    int t = threadIdx.x;
    float ang = (-2.0f * (float)M_PI / 512.0f) * (float)t;
    float s, c;
    sincosf(ang, &s, &c);
    g_tw[t] = make_float2(c, s);
}

// ---------------------------------------------------------------------------
// The shared 3-pass radix-8 512-pt FFT body. Column c = batch, u in 0..63.
// Ends with spectrum at natural index in sh[c][phys(k)].
// ---------------------------------------------------------------------------
__device__ __forceinline__ void fft512_body(float2 (*sh)[COLSZ], int c, int u,
                                            const float2 vh[4])
{
    float2 v[8], yo[8];
    // pass 1 (span 64, upper half zero)
    radix8_dif_half(vh, yo);
    sh[c][phys(u)] = yo[0];
    #pragma unroll
    for (int r = 1; r < 8; r++)
        sh[c][phys(64 * r + u)] = cmul(yo[r], g_tw[(u * r) & 511]);
    __syncthreads();

    // pass 2 (span 8)
    int g = u >> 3, q = u & 7;
    #pragma unroll
    for (int s = 0; s < 8; s++) v[s] = sh[c][phys(64 * g + q + 8 * s)];
    __syncthreads();
    radix8_dif(v, yo);
    sh[c][phys(64 * g + q)] = yo[0];
    #pragma unroll
    for (int r = 1; r < 8; r++)
        sh[c][phys(64 * g + 8 * r + q)] = cmul(yo[r], g_tw[(8 * q * r) & 511]);
    __syncthreads();

    // pass 3 (span 1), store at natural frequency index
    #pragma unroll
    for (int s = 0; s < 8; s++) v[s] = sh[c][phys(8 * u + s)];
    __syncthreads();
    radix8_dif(v, yo);
    int r1 = u >> 3, r2 = u & 7;
    #pragma unroll
    for (int r = 0; r < 8; r++)
        sh[c][phys(64 * r + 8 * r2 + r1)] = yo[r];
    __syncthreads();
}

// ---------------------------------------------------------------------------
// Stage A: apodize + row FFT. One block per y, all 8 batches (512 threads).
// ---------------------------------------------------------------------------
__global__ void __launch_bounds__(512) row_fft_kernel(
    const float* __restrict__ xr, const float* __restrict__ xi,
    const float* __restrict__ scy, const float* __restrict__ scx)
{
    __shared__ float2 sh[BATCH][COLSZ];
    int y = blockIdx.x;
    int t = threadIdx.x;
    int c = t >> 6;          // batch 0..7
    int u = t & 63;

    const float* rr = xr + ((size_t)c * HH + y) * WW;
    const float* ii = xi + ((size_t)c * HH + y) * WW;
    float syv = scy[y] * (1.0f / 512.0f);   // fold ortho 1/sqrt(GY*GX)

    float2 vh[4];
    #pragma unroll
    for (int s = 0; s < 4; s++) {
        int n = u + 64 * s;
        float sc = syv * scx[n];
        vh[s] = make_float2(rr[n] * sc, ii[n] * sc);
    }

    fft512_body(sh, c, u, vh);

    // coalesced writeout: tmp[y][kx][b]; 8 lanes -> 64B contiguous
    float2* outp = g_tmp + (size_t)y * GX * BATCH;
    #pragma unroll
    for (int it = 0; it < 8; it++) {
        int i  = it * 512 + t;
        int kx = i >> 3;
        int cc = i & 7;
        outp[(size_t)kx * BATCH + cc] = sh[cc][phys(kx)];
    }
}

// ---------------------------------------------------------------------------
// Stage B: column FFT. One block per x, all 8 batches (512 threads).
// Writes ghat as half2 (32B sector per 8-batch group).
// ---------------------------------------------------------------------------
__global__ void __launch_bounds__(512) col_fft_kernel()
{
    __shared__ float2 sh[BATCH][COLSZ];
    __shared__ float2 shin[BATCH][COLSZI];
    int x = blockIdx.x;
    int t = threadIdx.x;
    int c = t >> 6;
    int u = t & 63;

    // coalesced staging: 256 y x 8 b elements, 64B contiguous per 8 lanes
    const float2* inp = g_tmp + (size_t)x * BATCH;
    #pragma unroll
    for (int it = 0; it < 4; it++) {
        int i  = it * 512 + t;
        int yy = i >> 3;
        int cc = i & 7;
        shin[cc][physIn(yy)] = inp[(size_t)yy * GX * BATCH + cc];
    }
    __syncthreads();

    float2 vh[4];
    #pragma unroll
    for (int s = 0; s < 4; s++) vh[s] = shin[c][physIn(u + 64 * s)];

    fft512_body(sh, c, u, vh);

    // writeout: ghat[ky][x][b] half2; 8 lanes -> 32B full sector
    __half2* outp = g_ghat + (size_t)x * BATCH;
    #pragma unroll
    for (int it = 0; it < 8; it++) {
        int i  = it * 512 + t;
        int ky = i >> 3;
        int cc = i & 7;
        float2 vv = sh[cc][phys(ky)];
        outp[(size_t)ky * GX * BATCH + cc] = __floats2half2_rn(vv.x, vv.y);
    }
}

// ---------------------------------------------------------------------------
// Stage C: gather. Lane = (sample, batch). Tap for 8 batches = 8 half2 =
// one full 32B sector; per warp-inst 4 samples -> 4 sectors.
// ---------------------------------------------------------------------------
__global__ void __launch_bounds__(256) gather_kernel(
    const float* __restrict__ wy, const float* __restrict__ wx,
    const float* __restrict__ phr, const float* __restrict__ phi,
    const int* __restrict__ iy, const int* __restrict__ ix,
    float* __restrict__ out)
{
    int g = blockIdx.x * blockDim.x + threadIdx.x;
    if (g >= NS * BATCH) return;
    int n = g >> 3;
    int b = g & 7;

    int   ixv[JJ];
    float wxv[JJ];
    #pragma unroll
    for (int k = 0; k < JJ; k++) {
        ixv[k] = ix[(size_t)n * JJ + k];
        wxv[k] = wx[(size_t)n * JJ + k];
    }

    float ax = 0.f, ay = 0.f;
    #pragma unroll
    for (int j = 0; j < JJ; j++) {
        int   iyj = iy[(size_t)n * JJ + j];
        float wj  = wy[(size_t)n * JJ + j];
        const __half2* rowp = g_ghat + (size_t)iyj * GX * BATCH + b;
        #pragma unroll
        for (int k = 0; k < JJ; k++) {
            float2 vv = __half22float2(rowp[(size_t)ixv[k] * BATCH]);
            float  w  = wj * wxv[k];
            ax += w * vv.x;
            ay += w * vv.y;
        }
    }

    float pr = phr[n], pi = phi[n];
    float re = ax * pr - ay * pi;
    float im = ax * pi + ay * pr;
    float2* o = (float2*)(out + ((size_t)b * NS + n) * 2);
    *o = make_float2(re, im);
}

// ---------------------------------------------------------------------------
// inputs: 0:xr 1:xi 2:sc_y 3:sc_x 4:wy 5:wx 6:phr 7:phi 8:iy 9:ix
// ---------------------------------------------------------------------------
extern "C" void kernel_launch(void* const* d_in, const int* in_sizes, int n_in,
                              void* d_out, int out_size)
{
    const float* xr  = (const float*)d_in[0];
    const float* xi  = (const float*)d_in[1];
    const float* scy = (const float*)d_in[2];
    const float* scx = (const float*)d_in[3];
    const float* wy  = (const float*)d_in[4];
    const float* wx  = (const float*)d_in[5];
    const float* phr = (const float*)d_in[6];
    const float* phi = (const float*)d_in[7];
    const int*   iy  = (const int*)d_in[8];
    const int*   ix  = (const int*)d_in[9];
    float* out = (float*)d_out;

    init_kernel<<<1, 512>>>();

    row_fft_kernel<<<HH, 512>>>(xr, xi, scy, scx);

    col_fft_kernel<<<GX, 512>>>();

    int lanes = NS * BATCH;
    gather_kernel<<<(lanes + 255) / 256, 256>>>(wy, wx, phr, phi, iy, ix, out);
}